// round 4
// baseline (speedup 1.0000x reference)
#include <cuda_runtime.h>
#include <math.h>

// Problem constants
#define BATCH 128
#define CCH   512
#define HW    1024
#define EPSV  1e-5f

// GEMM tiling
#define BM 128
#define BN 128
#define BK 16
#define LDS (BM + 4)   // padded; row stride 528B (16B-aligned) to dodge conflicts

// Scratch (no allocations allowed -> __device__ globals)
__device__ float g_mu[BATCH];
__device__ float g_rstd[BATCH];
__device__ float g_hidden[(size_t)BATCH * HW * CCH];  // 256 MiB

// ---------------------------------------------------------------------------
// Kernel 1: per-sample mean / rstd over C*H*W = 524288 elements
// ---------------------------------------------------------------------------
__global__ __launch_bounds__(1024) void ln_stats_kernel(const float* __restrict__ x) {
    const int b = blockIdx.x;
    const float4* xb = reinterpret_cast<const float4*>(x) + (size_t)b * (CCH * HW / 4);
    float s = 0.f, ss = 0.f;
    for (int i = threadIdx.x; i < CCH * HW / 4; i += blockDim.x) {
        float4 v = xb[i];
        s  += (v.x + v.y) + (v.z + v.w);
        ss += (v.x * v.x + v.y * v.y) + (v.z * v.z + v.w * v.w);
    }
    #pragma unroll
    for (int o = 16; o; o >>= 1) {
        s  += __shfl_xor_sync(0xFFFFFFFFu, s, o);
        ss += __shfl_xor_sync(0xFFFFFFFFu, ss, o);
    }
    __shared__ float sh[2][32];
    const int w = threadIdx.x >> 5, l = threadIdx.x & 31;
    if (l == 0) { sh[0][w] = s; sh[1][w] = ss; }
    __syncthreads();
    if (w == 0) {
        s  = sh[0][l];
        ss = sh[1][l];
        #pragma unroll
        for (int o = 16; o; o >>= 1) {
            s  += __shfl_xor_sync(0xFFFFFFFFu, s, o);
            ss += __shfl_xor_sync(0xFFFFFFFFu, ss, o);
        }
        if (l == 0) {
            const float inv = 1.f / (float)(CCH * HW);
            const float mu  = s * inv;
            const float var = ss * inv - mu * mu;
            g_mu[b]   = mu;
            g_rstd[b] = rsqrtf(var + EPSV);
        }
    }
}

// ---------------------------------------------------------------------------
// helpers
// ---------------------------------------------------------------------------
__device__ __forceinline__ void fma44(float (&c)[4][4], float4 a, float4 b) {
    c[0][0] = fmaf(a.x, b.x, c[0][0]); c[0][1] = fmaf(a.x, b.y, c[0][1]);
    c[0][2] = fmaf(a.x, b.z, c[0][2]); c[0][3] = fmaf(a.x, b.w, c[0][3]);
    c[1][0] = fmaf(a.y, b.x, c[1][0]); c[1][1] = fmaf(a.y, b.y, c[1][1]);
    c[1][2] = fmaf(a.y, b.z, c[1][2]); c[1][3] = fmaf(a.y, b.w, c[1][3]);
    c[2][0] = fmaf(a.z, b.x, c[2][0]); c[2][1] = fmaf(a.z, b.y, c[2][1]);
    c[2][2] = fmaf(a.z, b.z, c[2][2]); c[2][3] = fmaf(a.z, b.w, c[2][3]);
    c[3][0] = fmaf(a.w, b.x, c[3][0]); c[3][1] = fmaf(a.w, b.y, c[3][1]);
    c[3][2] = fmaf(a.w, b.z, c[3][2]); c[3][3] = fmaf(a.w, b.w, c[3][3]);
}

__device__ __forceinline__ float4 ln4(float4 v, float4 lw, float4 lb, float mu, float rstd) {
    float4 r;
    r.x = (v.x - mu) * rstd * lw.x + lb.x;
    r.y = (v.y - mu) * rstd * lw.y + lb.y;
    r.z = (v.z - mu) * rstd * lw.z + lb.z;
    r.w = (v.w - mu) * rstd * lw.w + lb.w;
    return r;
}

// ---------------------------------------------------------------------------
// Kernel 2: GEMM1  hidden[m, d] = relu( sum_c xn[m, c] * w1[d, c] + b1[d] )
//   m = b*1024 + s; A element = LN(x[b, c, s]) fused at load time.
// ---------------------------------------------------------------------------
__global__ __launch_bounds__(256, 2) void gemm1_kernel(
    const float* __restrict__ x, const float* __restrict__ lnw,
    const float* __restrict__ lnb, const float* __restrict__ w1,
    const float* __restrict__ b1)
{
    __shared__ float As[BK][LDS];
    __shared__ float Bs[BK][LDS];

    const int tid = threadIdx.x;
    const int n0  = blockIdx.x * BN;
    const int m0  = blockIdx.y * BM;     // always within one sample (1024 % 128 == 0)
    const int b   = m0 >> 10;
    const int s0  = m0 & (HW - 1);
    const float mu   = g_mu[b];
    const float rstd = g_rstd[b];
    const float* xb  = x + (size_t)b * CCH * HW;

    // A loader: k = tid>>5 (0..7, +8), m = (tid&31)*4
    const int ak = tid >> 5;
    const int am = (tid & 31) << 2;
    // B loader: n = tid>>2 (0..63, +64), k = (tid&3)*4
    const int bn = tid >> 2;
    const int bk = (tid & 3) << 2;
    // compute coords (2x2 blocks of 4)
    const int cm = (tid & 15) << 2;
    const int cn = (tid >> 4) << 2;

    float acc[2][2][4][4] = {};

    const int KT = CCH / BK;  // 32
    #pragma unroll 1
    for (int kt = 0; kt < KT; kt++) {
        const int c0 = kt * BK;
        {
            float4 xv = *(const float4*)(xb  + (size_t)(c0 + ak) * HW + s0 + am);
            float4 lw = *(const float4*)(lnw + (size_t)(c0 + ak) * HW + s0 + am);
            float4 lb = *(const float4*)(lnb + (size_t)(c0 + ak) * HW + s0 + am);
            *(float4*)&As[ak][am] = ln4(xv, lw, lb, mu, rstd);
            xv = *(const float4*)(xb  + (size_t)(c0 + ak + 8) * HW + s0 + am);
            lw = *(const float4*)(lnw + (size_t)(c0 + ak + 8) * HW + s0 + am);
            lb = *(const float4*)(lnb + (size_t)(c0 + ak + 8) * HW + s0 + am);
            *(float4*)&As[ak + 8][am] = ln4(xv, lw, lb, mu, rstd);

            float4 wv = *(const float4*)(w1 + (size_t)(n0 + bn) * CCH + c0 + bk);
            Bs[bk + 0][bn] = wv.x; Bs[bk + 1][bn] = wv.y;
            Bs[bk + 2][bn] = wv.z; Bs[bk + 3][bn] = wv.w;
            wv = *(const float4*)(w1 + (size_t)(n0 + bn + 64) * CCH + c0 + bk);
            Bs[bk + 0][bn + 64] = wv.x; Bs[bk + 1][bn + 64] = wv.y;
            Bs[bk + 2][bn + 64] = wv.z; Bs[bk + 3][bn + 64] = wv.w;
        }
        __syncthreads();
        #pragma unroll
        for (int k = 0; k < BK; k++) {
            float4 a0 = *(const float4*)&As[k][cm];
            float4 a1 = *(const float4*)&As[k][cm + 64];
            float4 p0 = *(const float4*)&Bs[k][cn];
            float4 p1 = *(const float4*)&Bs[k][cn + 64];
            fma44(acc[0][0], a0, p0);
            fma44(acc[0][1], a0, p1);
            fma44(acc[1][0], a1, p0);
            fma44(acc[1][1], a1, p1);
        }
        __syncthreads();
    }

    // epilogue: bias + relu -> hidden[m][n] row-major
    float4 bv0 = *(const float4*)(b1 + n0 + cn);
    float4 bv1 = *(const float4*)(b1 + n0 + cn + 64);
    #pragma unroll
    for (int mg = 0; mg < 2; mg++) {
        #pragma unroll
        for (int i = 0; i < 4; i++) {
            const int m = m0 + cm + mg * 64 + i;
            float* hr = g_hidden + (size_t)m * CCH + n0;
            float4 o;
            o.x = fmaxf(acc[mg][0][i][0] + bv0.x, 0.f);
            o.y = fmaxf(acc[mg][0][i][1] + bv0.y, 0.f);
            o.z = fmaxf(acc[mg][0][i][2] + bv0.z, 0.f);
            o.w = fmaxf(acc[mg][0][i][3] + bv0.w, 0.f);
            *(float4*)(hr + cn) = o;
            o.x = fmaxf(acc[mg][1][i][0] + bv1.x, 0.f);
            o.y = fmaxf(acc[mg][1][i][1] + bv1.y, 0.f);
            o.z = fmaxf(acc[mg][1][i][2] + bv1.z, 0.f);
            o.w = fmaxf(acc[mg][1][i][3] + bv1.w, 0.f);
            *(float4*)(hr + cn + 64) = o;
        }
    }
}

// ---------------------------------------------------------------------------
// Kernel 3: GEMM2  out[b, e, s] = sum_d hidden[m, d] * w2[e, d] + b2[e]
// ---------------------------------------------------------------------------
__global__ __launch_bounds__(256, 2) void gemm2_kernel(
    const float* __restrict__ w2, const float* __restrict__ b2,
    float* __restrict__ out)
{
    __shared__ float As[BK][LDS];
    __shared__ float Bs[BK][LDS];

    const int tid = threadIdx.x;
    const int n0  = blockIdx.x * BN;
    const int m0  = blockIdx.y * BM;

    // loader coords (hidden and w2 are both [row][k], k contiguous)
    const int hm = tid >> 2;            // 0..63, +64
    const int hk = (tid & 3) << 2;      // 0,4,8,12
    const int cm = (tid & 15) << 2;
    const int cn = (tid >> 4) << 2;

    float acc[2][2][4][4] = {};

    const int KT = CCH / BK;  // 32
    #pragma unroll 1
    for (int kt = 0; kt < KT; kt++) {
        const int c0 = kt * BK;
        {
            float4 hv = *(const float4*)(g_hidden + (size_t)(m0 + hm) * CCH + c0 + hk);
            As[hk + 0][hm] = hv.x; As[hk + 1][hm] = hv.y;
            As[hk + 2][hm] = hv.z; As[hk + 3][hm] = hv.w;
            hv = *(const float4*)(g_hidden + (size_t)(m0 + hm + 64) * CCH + c0 + hk);
            As[hk + 0][hm + 64] = hv.x; As[hk + 1][hm + 64] = hv.y;
            As[hk + 2][hm + 64] = hv.z; As[hk + 3][hm + 64] = hv.w;

            float4 wv = *(const float4*)(w2 + (size_t)(n0 + hm) * CCH + c0 + hk);
            Bs[hk + 0][hm] = wv.x; Bs[hk + 1][hm] = wv.y;
            Bs[hk + 2][hm] = wv.z; Bs[hk + 3][hm] = wv.w;
            wv = *(const float4*)(w2 + (size_t)(n0 + hm + 64) * CCH + c0 + hk);
            Bs[hk + 0][hm + 64] = wv.x; Bs[hk + 1][hm + 64] = wv.y;
            Bs[hk + 2][hm + 64] = wv.z; Bs[hk + 3][hm + 64] = wv.w;
        }
        __syncthreads();
        #pragma unroll
        for (int k = 0; k < BK; k++) {
            float4 a0 = *(const float4*)&As[k][cm];
            float4 a1 = *(const float4*)&As[k][cm + 64];
            float4 p0 = *(const float4*)&Bs[k][cn];
            float4 p1 = *(const float4*)&Bs[k][cn + 64];
            fma44(acc[0][0], a0, p0);
            fma44(acc[0][1], a0, p1);
            fma44(acc[1][0], a1, p0);
            fma44(acc[1][1], a1, p1);
        }
        __syncthreads();
    }

    // epilogue: out[(b*C + n)*HW + s], s contiguous -> float4 stores
    float4 bv0 = *(const float4*)(b2 + n0 + cn);
    float4 bv1 = *(const float4*)(b2 + n0 + cn + 64);
    float bva[2][4] = {{bv0.x, bv0.y, bv0.z, bv0.w}, {bv1.x, bv1.y, bv1.z, bv1.w}};
    const int bidx = m0 >> 10;
    const int sb   = m0 & (HW - 1);
    float* ob = out + (size_t)bidx * CCH * HW;
    #pragma unroll
    for (int ng = 0; ng < 2; ng++) {
        #pragma unroll
        for (int j = 0; j < 4; j++) {
            const int n = n0 + cn + ng * 64 + j;
            const float bval = bva[ng][j];
            float* orow = ob + (size_t)n * HW + sb;
            #pragma unroll
            for (int mg = 0; mg < 2; mg++) {
                float4 o;
                o.x = acc[mg][ng][0][j] + bval;
                o.y = acc[mg][ng][1][j] + bval;
                o.z = acc[mg][ng][2][j] + bval;
                o.w = acc[mg][ng][3][j] + bval;
                *(float4*)(orow + cm + mg * 64) = o;
            }
        }
    }
}

// ---------------------------------------------------------------------------
// Input identification by element count (robust to metadata ordering):
//   x: 67108864, ln_w/ln_b: 524288 (in order), w1/w2: 262144 (in order),
//   b1/b2: 512 (in order)
// ---------------------------------------------------------------------------
extern "C" void kernel_launch(void* const* d_in, const int* in_sizes, int n_in,
                              void* d_out, int out_size) {
    const float* x = 0; const float* lnw = 0; const float* lnb = 0;
    const float* w1 = 0; const float* b1 = 0; const float* w2 = 0;
    const float* b2 = 0;
    for (int i = 0; i < n_in; i++) {
        const float* p = (const float*)d_in[i];
        switch (in_sizes[i]) {
            case 67108864: x = p; break;
            case 524288:   if (!lnw) lnw = p; else lnb = p; break;
            case 262144:   if (!w1)  w1  = p; else w2  = p; break;
            case 512:      if (!b1)  b1  = p; else b2  = p; break;
            default: break;
        }
    }
    float* out = (float*)d_out;

    ln_stats_kernel<<<BATCH, 1024>>>(x);
    dim3 grid(CCH / BN, (BATCH * HW) / BM);  // (4, 1024)
    gemm1_kernel<<<grid, 256>>>(x, lnw, lnb, w1, b1);
    gemm2_kernel<<<grid, 256>>>(w2, b2, out);
}

// round 9
// speedup vs baseline: 1.2338x; 1.2338x over previous
#include <cuda_runtime.h>
#include <cuda_bf16.h>
#include <stdint.h>
#include <math.h>

// Problem constants
#define BATCH 128
#define CCH   512
#define HW    1024
#define EPSV  1e-5f

// GEMM tiling: CTA 128x128, K-chunk 64, 8 warps of 64x32
#define BK      64
#define NCHUNK  (CCH / BK)    // 8
#define TILE_B  16384         // 128 rows x 128 bytes (bf16, SW128 rows)

#define OFF_AH  0
#define OFF_AL  16384
#define OFF_BH  32768
#define OFF_BL  49152
#define T_STRIDE 129
#define SMEM_TOTAL (128 * T_STRIDE * 4)   // 66048 >= 65536 mainloop need

// scratch (no allocs allowed)
__device__ float g_mu[BATCH];
__device__ float g_rstd[BATCH];
__device__ __nv_bfloat16 g_hid_hi[(size_t)BATCH * HW * CCH];  // 128 MiB
__device__ __nv_bfloat16 g_hid_lo[(size_t)BATCH * HW * CCH];  // 128 MiB

// ---------------------------------------------------------------------------
// helpers
// ---------------------------------------------------------------------------
__device__ __forceinline__ uint32_t smem_u32(const void* p) {
    uint32_t a;
    asm("{ .reg .u64 t; cvta.to.shared.u64 t, %1; cvt.u32.u64 %0, t; }" : "=r"(a) : "l"(p));
    return a;
}
__device__ __forceinline__ uint32_t swz(uint32_t off) { return off ^ ((off >> 3) & 0x70); }

__device__ __forceinline__ uint32_t bfpair(float a, float b) {
    __nv_bfloat162 t = __floats2bfloat162_rn(a, b);
    return *reinterpret_cast<uint32_t*>(&t);
}

__device__ __forceinline__ void ldsm4(uint32_t& r0, uint32_t& r1, uint32_t& r2,
                                      uint32_t& r3, uint32_t addr) {
    asm volatile("ldmatrix.sync.aligned.m8n8.x4.shared.b16 {%0,%1,%2,%3}, [%4];"
                 : "=r"(r0), "=r"(r1), "=r"(r2), "=r"(r3) : "r"(addr));
}

__device__ __forceinline__ void mma16816(float* c, const uint32_t* a,
                                         uint32_t b0, uint32_t b1) {
    asm volatile(
        "mma.sync.aligned.m16n8k16.row.col.f32.bf16.bf16.f32 "
        "{%0,%1,%2,%3}, {%4,%5,%6,%7}, {%8,%9}, {%0,%1,%2,%3};"
        : "+f"(c[0]), "+f"(c[1]), "+f"(c[2]), "+f"(c[3])
        : "r"(a[0]), "r"(a[1]), "r"(a[2]), "r"(a[3]), "r"(b0), "r"(b1));
}

// ---------------------------------------------------------------------------
// Kernel 1: per-sample mean / rstd (44us, 78% DRAM — near floor)
// ---------------------------------------------------------------------------
__global__ __launch_bounds__(1024) void ln_stats_kernel(const float* __restrict__ x) {
    const int b = blockIdx.x;
    const float4* xb = reinterpret_cast<const float4*>(x) + (size_t)b * (CCH * HW / 4);
    float s = 0.f, ss = 0.f;
    for (int i = threadIdx.x; i < CCH * HW / 4; i += blockDim.x) {
        float4 v = xb[i];
        s  += (v.x + v.y) + (v.z + v.w);
        ss += (v.x * v.x + v.y * v.y) + (v.z * v.z + v.w * v.w);
    }
    #pragma unroll
    for (int o = 16; o; o >>= 1) {
        s  += __shfl_xor_sync(0xFFFFFFFFu, s, o);
        ss += __shfl_xor_sync(0xFFFFFFFFu, ss, o);
    }
    __shared__ float sh[2][32];
    const int w = threadIdx.x >> 5, l = threadIdx.x & 31;
    if (l == 0) { sh[0][w] = s; sh[1][w] = ss; }
    __syncthreads();
    if (w == 0) {
        s = sh[0][l]; ss = sh[1][l];
        #pragma unroll
        for (int o = 16; o; o >>= 1) {
            s  += __shfl_xor_sync(0xFFFFFFFFu, s, o);
            ss += __shfl_xor_sync(0xFFFFFFFFu, ss, o);
        }
        if (l == 0) {
            const float inv = 1.f / (float)(CCH * HW);
            const float mu = s * inv;
            const float var = ss * inv - mu * mu;
            g_mu[b] = mu;
            g_rstd[b] = rsqrtf(var + EPSV);
        }
    }
}

// ---------------------------------------------------------------------------
// GEMM1 (HMMA): hidden = relu(LN(x) @ w1^T + b1) -> bf16 hi/lo planes
// ---------------------------------------------------------------------------
__global__ __launch_bounds__(256, 2) void gemm1_tc(
    const float* __restrict__ x, const float* __restrict__ lnw,
    const float* __restrict__ lnb, const float* __restrict__ w1,
    const float* __restrict__ b1)
{
    extern __shared__ char smem[];
    const uint32_t sbase = smem_u32(smem);
    const int tid = threadIdx.x;
    const int wid = tid >> 5, lane = tid & 31;

    const int n0 = blockIdx.x * 128;
    const int m0 = blockIdx.y * 128;
    const int b  = m0 >> 10;
    const int s0 = m0 & (HW - 1);
    const float mu = g_mu[b], rstd = g_rstd[b];
    const float* xb = x + (size_t)b * CCH * HW;

    const int warp_m = (wid & 1) * 64;
    const int warp_n = (wid >> 1) * 32;

    float acc[4][4][4];
    #pragma unroll
    for (int i = 0; i < 4; i++)
        #pragma unroll
        for (int j = 0; j < 4; j++)
            #pragma unroll
            for (int k = 0; k < 4; k++) acc[i][j][k] = 0.f;

    const int lc4 = (tid & 15) * 4;     // A loader: 4 channels
    const int lmr = (tid >> 4) * 8;     // A loader: 8 tokens
    const int bn_ = tid >> 1;           // B loader: n row
    const int bh_ = (tid & 1) * 32;     // B loader: k half (floats)

    #pragma unroll 1
    for (int kt = 0; kt < NCHUNK; kt++) {
        const int c0 = kt * BK;
        // ---- A tile: LN(x) fused, split, transposed scatter to [m][c] ----
        #pragma unroll
        for (int cc = 0; cc < 4; cc++) {
            const int c = c0 + lc4 + cc;
            const size_t rb = (size_t)c * HW + s0 + lmr;
            float4 x0 = *(const float4*)(xb + rb);
            float4 x1 = *(const float4*)(xb + rb + 4);
            float4 w0 = *(const float4*)(lnw + rb);
            float4 w1v = *(const float4*)(lnw + rb + 4);
            float4 e0 = *(const float4*)(lnb + rb);
            float4 e1 = *(const float4*)(lnb + rb + 4);
            float vals[8];
            vals[0] = fmaf((x0.x - mu) * rstd, w0.x, e0.x);
            vals[1] = fmaf((x0.y - mu) * rstd, w0.y, e0.y);
            vals[2] = fmaf((x0.z - mu) * rstd, w0.z, e0.z);
            vals[3] = fmaf((x0.w - mu) * rstd, w0.w, e0.w);
            vals[4] = fmaf((x1.x - mu) * rstd, w1v.x, e1.x);
            vals[5] = fmaf((x1.y - mu) * rstd, w1v.y, e1.y);
            vals[6] = fmaf((x1.z - mu) * rstd, w1v.z, e1.z);
            vals[7] = fmaf((x1.w - mu) * rstd, w1v.w, e1.w);
            #pragma unroll
            for (int j = 0; j < 8; j++) {
                __nv_bfloat16 h = __float2bfloat16(vals[j]);
                __nv_bfloat16 l = __float2bfloat16(vals[j] - __bfloat162float(h));
                const uint32_t off = swz((uint32_t)((lmr + j) * 128 + (lc4 + cc) * 2));
                *(__nv_bfloat16*)(smem + OFF_AH + off) = h;
                *(__nv_bfloat16*)(smem + OFF_AL + off) = l;
            }
        }
        // ---- B tile: w1[n][k] split, k-contiguous 16B stores ----
        {
            const float* wr = w1 + (size_t)(n0 + bn_) * CCH + c0 + bh_;
            #pragma unroll
            for (int ch = 0; ch < 4; ch++) {
                float4 u0 = *(const float4*)(wr + ch * 8);
                float4 u1 = *(const float4*)(wr + ch * 8 + 4);
                float v[8] = {u0.x, u0.y, u0.z, u0.w, u1.x, u1.y, u1.z, u1.w};
                float hf[8];
                #pragma unroll
                for (int j = 0; j < 8; j++)
                    hf[j] = __bfloat162float(__float2bfloat16(v[j]));
                uint4 hi = make_uint4(bfpair(v[0], v[1]), bfpair(v[2], v[3]),
                                      bfpair(v[4], v[5]), bfpair(v[6], v[7]));
                uint4 lo = make_uint4(bfpair(v[0]-hf[0], v[1]-hf[1]), bfpair(v[2]-hf[2], v[3]-hf[3]),
                                      bfpair(v[4]-hf[4], v[5]-hf[5]), bfpair(v[6]-hf[6], v[7]-hf[7]));
                const uint32_t off = swz((uint32_t)(bn_ * 128 + ((bh_ >> 3) + ch) * 16));
                *(uint4*)(smem + OFF_BH + off) = hi;
                *(uint4*)(smem + OFF_BL + off) = lo;
            }
        }
        __syncthreads();
        // ---- compute: 4 k-steps of 16, 3-term split ----
        #pragma unroll
        for (int ks = 0; ks < 4; ks++) {
            uint32_t bhf[8], blf[8];
            #pragma unroll
            for (int g = 0; g < 2; g++) {
                const int nrow = warp_n + g * 16 + (lane & 7) + ((lane >> 4) & 1) * 8;
                const int chunk = ks * 2 + ((lane >> 3) & 1);
                const uint32_t off = swz((uint32_t)(nrow * 128 + chunk * 16));
                ldsm4(bhf[g*4+0], bhf[g*4+1], bhf[g*4+2], bhf[g*4+3], sbase + OFF_BH + off);
                ldsm4(blf[g*4+0], blf[g*4+1], blf[g*4+2], blf[g*4+3], sbase + OFF_BL + off);
            }
            #pragma unroll
            for (int mf = 0; mf < 4; mf++) {
                const int mrow = warp_m + mf * 16 + (lane & 15);
                const int chunk = ks * 2 + (lane >> 4);
                const uint32_t off = swz((uint32_t)(mrow * 128 + chunk * 16));
                uint32_t ah[4], al[4];
                ldsm4(ah[0], ah[1], ah[2], ah[3], sbase + OFF_AH + off);
                ldsm4(al[0], al[1], al[2], al[3], sbase + OFF_AL + off);
                #pragma unroll
                for (int nf = 0; nf < 4; nf++) {
                    mma16816(acc[mf][nf], ah, bhf[nf*2], bhf[nf*2+1]);
                    mma16816(acc[mf][nf], ah, blf[nf*2], blf[nf*2+1]);
                    mma16816(acc[mf][nf], al, bhf[nf*2], bhf[nf*2+1]);
                }
            }
        }
        __syncthreads();
    }

    // ---- epilogue: bias + relu + split -> hi/lo planes (register-direct) ----
    #pragma unroll
    for (int mf = 0; mf < 4; mf++) {
        #pragma unroll
        for (int nf = 0; nf < 4; nf++) {
            const int rm = warp_m + mf * 16 + (lane >> 2);
            const int cn = warp_n + nf * 8 + (lane & 3) * 2;
            const float bv0 = b1[n0 + cn], bv1 = b1[n0 + cn + 1];
            float v00 = fmaxf(acc[mf][nf][0] + bv0, 0.f);
            float v01 = fmaxf(acc[mf][nf][1] + bv1, 0.f);
            float v10 = fmaxf(acc[mf][nf][2] + bv0, 0.f);
            float v11 = fmaxf(acc[mf][nf][3] + bv1, 0.f);
            const size_t base0 = (size_t)(m0 + rm) * CCH + n0 + cn;
            const size_t base1 = base0 + 8 * CCH;
            float h00 = __bfloat162float(__float2bfloat16(v00));
            float h01 = __bfloat162float(__float2bfloat16(v01));
            float h10 = __bfloat162float(__float2bfloat16(v10));
            float h11 = __bfloat162float(__float2bfloat16(v11));
            *(uint32_t*)(g_hid_hi + base0) = bfpair(v00, v01);
            *(uint32_t*)(g_hid_lo + base0) = bfpair(v00 - h00, v01 - h01);
            *(uint32_t*)(g_hid_hi + base1) = bfpair(v10, v11);
            *(uint32_t*)(g_hid_lo + base1) = bfpair(v10 - h10, v11 - h11);
        }
    }
}

// ---------------------------------------------------------------------------
// GEMM2 (HMMA): out[b,e,s] = hidden @ w2^T + b2  (smem-transpose epilogue)
// ---------------------------------------------------------------------------
__global__ __launch_bounds__(256, 2) void gemm2_tc(
    const float* __restrict__ w2, const float* __restrict__ b2,
    float* __restrict__ out)
{
    extern __shared__ char smem[];
    const uint32_t sbase = smem_u32(smem);
    const int tid = threadIdx.x;
    const int wid = tid >> 5, lane = tid & 31;

    const int n0 = blockIdx.x * 128;
    const int m0 = blockIdx.y * 128;

    const int warp_m = (wid & 1) * 64;
    const int warp_n = (wid >> 1) * 32;

    float acc[4][4][4];
    #pragma unroll
    for (int i = 0; i < 4; i++)
        #pragma unroll
        for (int j = 0; j < 4; j++)
            #pragma unroll
            for (int k = 0; k < 4; k++) acc[i][j][k] = 0.f;

    const int hm_ = tid >> 1;           // A loader: m row
    const int hh_ = (tid & 1) * 4;      // A loader: chunk base (4 chunks each)
    const int bn_ = tid >> 1;
    const int bh_ = (tid & 1) * 32;

    #pragma unroll 1
    for (int kt = 0; kt < NCHUNK; kt++) {
        const int c0 = kt * BK;
        // ---- A tile: hidden planes, direct 16B copies ----
        {
            const size_t abase = (size_t)(m0 + hm_) * CCH + c0 + hh_ * 8;
            #pragma unroll
            for (int ch = 0; ch < 4; ch++) {
                uint4 h4 = *(const uint4*)(g_hid_hi + abase + ch * 8);
                uint4 l4 = *(const uint4*)(g_hid_lo + abase + ch * 8);
                const uint32_t off = swz((uint32_t)(hm_ * 128 + (hh_ + ch) * 16));
                *(uint4*)(smem + OFF_AH + off) = h4;
                *(uint4*)(smem + OFF_AL + off) = l4;
            }
        }
        // ---- B tile: w2 split ----
        {
            const float* wr = w2 + (size_t)(n0 + bn_) * CCH + c0 + bh_;
            #pragma unroll
            for (int ch = 0; ch < 4; ch++) {
                float4 u0 = *(const float4*)(wr + ch * 8);
                float4 u1 = *(const float4*)(wr + ch * 8 + 4);
                float v[8] = {u0.x, u0.y, u0.z, u0.w, u1.x, u1.y, u1.z, u1.w};
                float hf[8];
                #pragma unroll
                for (int j = 0; j < 8; j++)
                    hf[j] = __bfloat162float(__float2bfloat16(v[j]));
                uint4 hi = make_uint4(bfpair(v[0], v[1]), bfpair(v[2], v[3]),
                                      bfpair(v[4], v[5]), bfpair(v[6], v[7]));
                uint4 lo = make_uint4(bfpair(v[0]-hf[0], v[1]-hf[1]), bfpair(v[2]-hf[2], v[3]-hf[3]),
                                      bfpair(v[4]-hf[4], v[5]-hf[5]), bfpair(v[6]-hf[6], v[7]-hf[7]));
                const uint32_t off = swz((uint32_t)(bn_ * 128 + ((bh_ >> 3) + ch) * 16));
                *(uint4*)(smem + OFF_BH + off) = hi;
                *(uint4*)(smem + OFF_BL + off) = lo;
            }
        }
        __syncthreads();
        #pragma unroll
        for (int ks = 0; ks < 4; ks++) {
            uint32_t bhf[8], blf[8];
            #pragma unroll
            for (int g = 0; g < 2; g++) {
                const int nrow = warp_n + g * 16 + (lane & 7) + ((lane >> 4) & 1) * 8;
                const int chunk = ks * 2 + ((lane >> 3) & 1);
                const uint32_t off = swz((uint32_t)(nrow * 128 + chunk * 16));
                ldsm4(bhf[g*4+0], bhf[g*4+1], bhf[g*4+2], bhf[g*4+3], sbase + OFF_BH + off);
                ldsm4(blf[g*4+0], blf[g*4+1], blf[g*4+2], blf[g*4+3], sbase + OFF_BL + off);
            }
            #pragma unroll
            for (int mf = 0; mf < 4; mf++) {
                const int mrow = warp_m + mf * 16 + (lane & 15);
                const int chunk = ks * 2 + (lane >> 4);
                const uint32_t off = swz((uint32_t)(mrow * 128 + chunk * 16));
                uint32_t ah[4], al[4];
                ldsm4(ah[0], ah[1], ah[2], ah[3], sbase + OFF_AH + off);
                ldsm4(al[0], al[1], al[2], al[3], sbase + OFF_AL + off);
                #pragma unroll
                for (int nf = 0; nf < 4; nf++) {
                    mma16816(acc[mf][nf], ah, bhf[nf*2], bhf[nf*2+1]);
                    mma16816(acc[mf][nf], ah, blf[nf*2], blf[nf*2+1]);
                    mma16816(acc[mf][nf], al, bhf[nf*2], bhf[nf*2+1]);
                }
            }
        }
        __syncthreads();
    }

    // ---- epilogue: acc -> smem T[m][e] -> transposed coalesced out stores ----
    float* T = (float*)smem;
    #pragma unroll
    for (int mf = 0; mf < 4; mf++) {
        #pragma unroll
        for (int nf = 0; nf < 4; nf++) {
            const int rm = warp_m + mf * 16 + (lane >> 2);
            const int cn = warp_n + nf * 8 + (lane & 3) * 2;
            T[rm * T_STRIDE + cn]           = acc[mf][nf][0];
            T[rm * T_STRIDE + cn + 1]       = acc[mf][nf][1];
            T[(rm + 8) * T_STRIDE + cn]     = acc[mf][nf][2];
            T[(rm + 8) * T_STRIDE + cn + 1] = acc[mf][nf][3];
        }
    }
    __syncthreads();
    {
        const int e    = tid & 127;
        const int half = tid >> 7;
        const int bidx = m0 >> 10;
        const int sb   = m0 & (HW - 1);
        const float bv = b2[n0 + e];
        float* orow = out + ((size_t)bidx * CCH + n0 + e) * HW + sb + half * 64;
        #pragma unroll
        for (int grp = 0; grp < 16; grp++) {
            const int mb = half * 64 + grp * 4;
            float4 o;
            o.x = T[(mb + 0) * T_STRIDE + e] + bv;
            o.y = T[(mb + 1) * T_STRIDE + e] + bv;
            o.z = T[(mb + 2) * T_STRIDE + e] + bv;
            o.w = T[(mb + 3) * T_STRIDE + e] + bv;
            *(float4*)(orow + grp * 4) = o;
        }
    }
}

// ---------------------------------------------------------------------------
extern "C" void kernel_launch(void* const* d_in, const int* in_sizes, int n_in,
                              void* d_out, int out_size) {
    const float* x = 0; const float* lnw = 0; const float* lnb = 0;
    const float* w1 = 0; const float* b1 = 0; const float* w2 = 0;
    const float* b2 = 0;
    for (int i = 0; i < n_in; i++) {
        const float* p = (const float*)d_in[i];
        switch (in_sizes[i]) {
            case 67108864: x = p; break;
            case 524288:   if (!lnw) lnw = p; else lnb = p; break;
            case 262144:   if (!w1)  w1  = p; else w2  = p; break;
            case 512:      if (!b1)  b1  = p; else b2  = p; break;
            default: break;
        }
    }
    float* out = (float*)d_out;

    cudaFuncSetAttribute(gemm1_tc, cudaFuncAttributeMaxDynamicSharedMemorySize, SMEM_TOTAL);
    cudaFuncSetAttribute(gemm2_tc, cudaFuncAttributeMaxDynamicSharedMemorySize, SMEM_TOTAL);

    ln_stats_kernel<<<BATCH, 1024>>>(x);
    dim3 grid(CCH / 128, (BATCH * HW) / 128);  // (4, 1024)
    gemm1_tc<<<grid, 256, SMEM_TOTAL>>>(x, lnw, lnb, w1, b1);
    gemm2_tc<<<grid, 256, SMEM_TOTAL>>>(w2, b2, out);
}

// round 12
// speedup vs baseline: 1.8113x; 1.4680x over previous
#include <cuda_runtime.h>
#include <cuda_bf16.h>
#include <stdint.h>
#include <math.h>

// Problem constants
#define BATCH 128
#define CCH   512
#define HW    1024
#define EPSV  1e-5f

// GEMM tiling: CTA 128x128, K-chunk 64, 8 warps of 64x32
#define BK      64
#define NCHUNK  (CCH / BK)    // 8

#define OFF_AH  0
#define OFF_AL  16384
#define OFF_BH  32768
#define OFF_BL  49152
#define T_STRIDE 129
#define SMEM_TOTAL (128 * T_STRIDE * 4)   // 66048 >= 65536 mainloop need

// scratch (no allocs allowed)
__device__ float g_mu[BATCH];
__device__ float g_rstd[BATCH];
__device__ __nv_bfloat16 g_a_hi[(size_t)BATCH * HW * CCH];    // 128 MiB  LN(x) hi
__device__ __nv_bfloat16 g_a_lo[(size_t)BATCH * HW * CCH];    // 128 MiB  LN(x) lo
__device__ __nv_bfloat16 g_hid_hi[(size_t)BATCH * HW * CCH];  // 128 MiB
__device__ __nv_bfloat16 g_hid_lo[(size_t)BATCH * HW * CCH];  // 128 MiB
__device__ __nv_bfloat16 g_w1_hi[CCH * CCH];
__device__ __nv_bfloat16 g_w1_lo[CCH * CCH];
__device__ __nv_bfloat16 g_w2_hi[CCH * CCH];
__device__ __nv_bfloat16 g_w2_lo[CCH * CCH];

// ---------------------------------------------------------------------------
// helpers
// ---------------------------------------------------------------------------
__device__ __forceinline__ uint32_t smem_u32(const void* p) {
    uint32_t a;
    asm("{ .reg .u64 t; cvta.to.shared.u64 t, %1; cvt.u32.u64 %0, t; }" : "=r"(a) : "l"(p));
    return a;
}
__device__ __forceinline__ uint32_t swz(uint32_t off) { return off ^ ((off >> 3) & 0x70); }

__device__ __forceinline__ uint32_t bfpair(float a, float b) {
    __nv_bfloat162 t = __floats2bfloat162_rn(a, b);
    return *reinterpret_cast<uint32_t*>(&t);
}

__device__ __forceinline__ void cpasync16(uint32_t saddr, const void* gptr) {
    asm volatile("cp.async.cg.shared.global [%0], [%1], 16;" :: "r"(saddr), "l"(gptr));
}
#define CP_COMMIT() asm volatile("cp.async.commit_group;" ::: "memory")
#define CP_WAIT0()  asm volatile("cp.async.wait_group 0;" ::: "memory")

__device__ __forceinline__ void ldsm4(uint32_t& r0, uint32_t& r1, uint32_t& r2,
                                      uint32_t& r3, uint32_t addr) {
    asm volatile("ldmatrix.sync.aligned.m8n8.x4.shared.b16 {%0,%1,%2,%3}, [%4];"
                 : "=r"(r0), "=r"(r1), "=r"(r2), "=r"(r3) : "r"(addr));
}

__device__ __forceinline__ void mma16816(float* c, const uint32_t* a,
                                         uint32_t b0, uint32_t b1) {
    asm volatile(
        "mma.sync.aligned.m16n8k16.row.col.f32.bf16.bf16.f32 "
        "{%0,%1,%2,%3}, {%4,%5,%6,%7}, {%8,%9}, {%0,%1,%2,%3};"
        : "+f"(c[0]), "+f"(c[1]), "+f"(c[2]), "+f"(c[3])
        : "r"(a[0]), "r"(a[1]), "r"(a[2]), "r"(a[3]), "r"(b0), "r"(b1));
}

// ---------------------------------------------------------------------------
// Kernel 1: per-sample mean / rstd
// ---------------------------------------------------------------------------
__global__ __launch_bounds__(1024) void ln_stats_kernel(const float* __restrict__ x) {
    const int b = blockIdx.x;
    const float4* xb = reinterpret_cast<const float4*>(x) + (size_t)b * (CCH * HW / 4);
    float s = 0.f, ss = 0.f;
    for (int i = threadIdx.x; i < CCH * HW / 4; i += blockDim.x) {
        float4 v = xb[i];
        s  += (v.x + v.y) + (v.z + v.w);
        ss += (v.x * v.x + v.y * v.y) + (v.z * v.z + v.w * v.w);
    }
    #pragma unroll
    for (int o = 16; o; o >>= 1) {
        s  += __shfl_xor_sync(0xFFFFFFFFu, s, o);
        ss += __shfl_xor_sync(0xFFFFFFFFu, ss, o);
    }
    __shared__ float sh[2][32];
    const int w = threadIdx.x >> 5, l = threadIdx.x & 31;
    if (l == 0) { sh[0][w] = s; sh[1][w] = ss; }
    __syncthreads();
    if (w == 0) {
        s = sh[0][l]; ss = sh[1][l];
        #pragma unroll
        for (int o = 16; o; o >>= 1) {
            s  += __shfl_xor_sync(0xFFFFFFFFu, s, o);
            ss += __shfl_xor_sync(0xFFFFFFFFu, ss, o);
        }
        if (l == 0) {
            const float inv = 1.f / (float)(CCH * HW);
            const float mu = s * inv;
            const float var = ss * inv - mu * mu;
            g_mu[b] = mu;
            g_rstd[b] = rsqrtf(var + EPSV);
        }
    }
}

// ---------------------------------------------------------------------------
// prep_w: split w1/w2 to bf16 hi/lo planes (once)
// ---------------------------------------------------------------------------
__global__ __launch_bounds__(256) void prep_w_kernel(const float* __restrict__ w1,
                                                     const float* __restrict__ w2) {
    const int idx = (blockIdx.x * 256 + threadIdx.x) * 4;   // grid 256 -> covers 262144
    {
        float4 v = *(const float4*)(w1 + idx);
        float h0 = __bfloat162float(__float2bfloat16(v.x));
        float h1 = __bfloat162float(__float2bfloat16(v.y));
        float h2 = __bfloat162float(__float2bfloat16(v.z));
        float h3 = __bfloat162float(__float2bfloat16(v.w));
        *(uint2*)(g_w1_hi + idx) = make_uint2(bfpair(v.x, v.y), bfpair(v.z, v.w));
        *(uint2*)(g_w1_lo + idx) = make_uint2(bfpair(v.x - h0, v.y - h1), bfpair(v.z - h2, v.w - h3));
    }
    {
        float4 v = *(const float4*)(w2 + idx);
        float h0 = __bfloat162float(__float2bfloat16(v.x));
        float h1 = __bfloat162float(__float2bfloat16(v.y));
        float h2 = __bfloat162float(__float2bfloat16(v.z));
        float h3 = __bfloat162float(__float2bfloat16(v.w));
        *(uint2*)(g_w2_hi + idx) = make_uint2(bfpair(v.x, v.y), bfpair(v.z, v.w));
        *(uint2*)(g_w2_lo + idx) = make_uint2(bfpair(v.x - h0, v.y - h1), bfpair(v.z - h2, v.w - h3));
    }
}

// ---------------------------------------------------------------------------
// prep_a: LN(x) -> bf16 hi/lo planes in [m][c] (k-contiguous) layout (once)
//   block = 128 tokens; thread (tid&15)->4 channels, (tid>>4)->8 tokens
// ---------------------------------------------------------------------------
__global__ __launch_bounds__(256) void prep_a_kernel(
    const float* __restrict__ x, const float* __restrict__ lnw,
    const float* __restrict__ lnb)
{
    const int m0 = blockIdx.x * 128;
    const int b  = m0 >> 10;
    const int s0 = m0 & (HW - 1);
    const float mu = g_mu[b], rstd = g_rstd[b];
    const float* xb = x + (size_t)b * CCH * HW;

    const int lc4 = (threadIdx.x & 15) * 4;
    const int lmr = (threadIdx.x >> 4) * 8;

    #pragma unroll 1
    for (int p = 0; p < 8; p++) {
        const int cbase = p * 64 + lc4;
        float vals[4][8];
        #pragma unroll
        for (int cc = 0; cc < 4; cc++) {
            const size_t rb = (size_t)(cbase + cc) * HW + s0 + lmr;
            float4 x0 = *(const float4*)(xb + rb);
            float4 x1 = *(const float4*)(xb + rb + 4);
            float4 w0 = *(const float4*)(lnw + rb);
            float4 w1v = *(const float4*)(lnw + rb + 4);
            float4 e0 = *(const float4*)(lnb + rb);
            float4 e1 = *(const float4*)(lnb + rb + 4);
            vals[cc][0] = fmaf((x0.x - mu) * rstd, w0.x, e0.x);
            vals[cc][1] = fmaf((x0.y - mu) * rstd, w0.y, e0.y);
            vals[cc][2] = fmaf((x0.z - mu) * rstd, w0.z, e0.z);
            vals[cc][3] = fmaf((x0.w - mu) * rstd, w0.w, e0.w);
            vals[cc][4] = fmaf((x1.x - mu) * rstd, w1v.x, e1.x);
            vals[cc][5] = fmaf((x1.y - mu) * rstd, w1v.y, e1.y);
            vals[cc][6] = fmaf((x1.z - mu) * rstd, w1v.z, e1.z);
            vals[cc][7] = fmaf((x1.w - mu) * rstd, w1v.w, e1.w);
        }
        #pragma unroll
        for (int j = 0; j < 8; j++) {
            const size_t base = (size_t)(m0 + lmr + j) * CCH + cbase;
            float v0 = vals[0][j], v1 = vals[1][j], v2 = vals[2][j], v3 = vals[3][j];
            float h0 = __bfloat162float(__float2bfloat16(v0));
            float h1 = __bfloat162float(__float2bfloat16(v1));
            float h2 = __bfloat162float(__float2bfloat16(v2));
            float h3 = __bfloat162float(__float2bfloat16(v3));
            *(uint2*)(g_a_hi + base) = make_uint2(bfpair(v0, v1), bfpair(v2, v3));
            *(uint2*)(g_a_lo + base) = make_uint2(bfpair(v0 - h0, v1 - h1), bfpair(v2 - h2, v3 - h3));
        }
    }
}

// ---------------------------------------------------------------------------
// Shared mainloop body: cp.async copy loaders + ldsm/mma (verified mapping)
// ---------------------------------------------------------------------------
__device__ __forceinline__ void gemm_mainloop(
    char* smem, uint32_t sbase, int tid, int lane,
    int warp_m, int warp_n, int m0, int n0,
    const __nv_bfloat16* __restrict__ a_hi, const __nv_bfloat16* __restrict__ a_lo,
    const __nv_bfloat16* __restrict__ w_hi, const __nv_bfloat16* __restrict__ w_lo,
    float acc[4][4][4])
{
    const int row_ = tid >> 1;          // loader row (m for A, n for B)
    const int ch0  = (tid & 1) * 4;     // 16B chunk base (4 chunks each)

    #pragma unroll 1
    for (int kt = 0; kt < NCHUNK; kt++) {
        const int c0 = kt * BK;
        // ---- loaders: pure 16B cp.async copies ----
        const size_t ab = (size_t)(m0 + row_) * CCH + c0;
        const size_t bb = (size_t)(n0 + row_) * CCH + c0;
        #pragma unroll
        for (int ch = 0; ch < 4; ch++) {
            const uint32_t off = swz((uint32_t)(row_ * 128 + (ch0 + ch) * 16));
            const int eo = (ch0 + ch) * 8;
            cpasync16(sbase + OFF_AH + off, a_hi + ab + eo);
            cpasync16(sbase + OFF_AL + off, a_lo + ab + eo);
            cpasync16(sbase + OFF_BH + off, w_hi + bb + eo);
            cpasync16(sbase + OFF_BL + off, w_lo + bb + eo);
        }
        CP_COMMIT();
        CP_WAIT0();
        __syncthreads();
        // ---- compute: 4 k-steps of 16, 3-term split ----
        #pragma unroll
        for (int ks = 0; ks < 4; ks++) {
            uint32_t bhf[8], blf[8];
            #pragma unroll
            for (int g = 0; g < 2; g++) {
                const int nrow = warp_n + g * 16 + (lane & 7) + ((lane >> 4) & 1) * 8;
                const int chunk = ks * 2 + ((lane >> 3) & 1);
                const uint32_t off = swz((uint32_t)(nrow * 128 + chunk * 16));
                ldsm4(bhf[g*4+0], bhf[g*4+1], bhf[g*4+2], bhf[g*4+3], sbase + OFF_BH + off);
                ldsm4(blf[g*4+0], blf[g*4+1], blf[g*4+2], blf[g*4+3], sbase + OFF_BL + off);
            }
            #pragma unroll
            for (int mf = 0; mf < 4; mf++) {
                const int mrow = warp_m + mf * 16 + (lane & 15);
                const int chunk = ks * 2 + (lane >> 4);
                const uint32_t off = swz((uint32_t)(mrow * 128 + chunk * 16));
                uint32_t ah[4], al[4];
                ldsm4(ah[0], ah[1], ah[2], ah[3], sbase + OFF_AH + off);
                ldsm4(al[0], al[1], al[2], al[3], sbase + OFF_AL + off);
                #pragma unroll
                for (int nf = 0; nf < 4; nf++) {
                    mma16816(acc[mf][nf], ah, bhf[nf*2], bhf[nf*2+1]);
                    mma16816(acc[mf][nf], ah, blf[nf*2], blf[nf*2+1]);
                    mma16816(acc[mf][nf], al, bhf[nf*2], bhf[nf*2+1]);
                }
            }
        }
        __syncthreads();
    }
}

// ---------------------------------------------------------------------------
// GEMM1 (HMMA): hidden = relu(a @ w1^T + b1) -> bf16 hi/lo planes
// ---------------------------------------------------------------------------
__global__ __launch_bounds__(256, 2) void gemm1_tc(const float* __restrict__ b1) {
    extern __shared__ char smem[];
    const uint32_t sbase = smem_u32(smem);
    const int tid = threadIdx.x;
    const int wid = tid >> 5, lane = tid & 31;
    const int n0 = blockIdx.x * 128;
    const int m0 = blockIdx.y * 128;
    const int warp_m = (wid & 1) * 64;
    const int warp_n = (wid >> 1) * 32;

    float acc[4][4][4];
    #pragma unroll
    for (int i = 0; i < 4; i++)
        #pragma unroll
        for (int j = 0; j < 4; j++)
            #pragma unroll
            for (int k = 0; k < 4; k++) acc[i][j][k] = 0.f;

    gemm_mainloop(smem, sbase, tid, lane, warp_m, warp_n, m0, n0,
                  g_a_hi, g_a_lo, g_w1_hi, g_w1_lo, acc);

    // ---- epilogue: bias + relu + split -> hidden planes (register-direct) ----
    #pragma unroll
    for (int mf = 0; mf < 4; mf++) {
        #pragma unroll
        for (int nf = 0; nf < 4; nf++) {
            const int rm = warp_m + mf * 16 + (lane >> 2);
            const int cn = warp_n + nf * 8 + (lane & 3) * 2;
            const float bv0 = b1[n0 + cn], bv1 = b1[n0 + cn + 1];
            float v00 = fmaxf(acc[mf][nf][0] + bv0, 0.f);
            float v01 = fmaxf(acc[mf][nf][1] + bv1, 0.f);
            float v10 = fmaxf(acc[mf][nf][2] + bv0, 0.f);
            float v11 = fmaxf(acc[mf][nf][3] + bv1, 0.f);
            const size_t base0 = (size_t)(m0 + rm) * CCH + n0 + cn;
            const size_t base1 = base0 + 8 * CCH;
            float h00 = __bfloat162float(__float2bfloat16(v00));
            float h01 = __bfloat162float(__float2bfloat16(v01));
            float h10 = __bfloat162float(__float2bfloat16(v10));
            float h11 = __bfloat162float(__float2bfloat16(v11));
            *(uint32_t*)(g_hid_hi + base0) = bfpair(v00, v01);
            *(uint32_t*)(g_hid_lo + base0) = bfpair(v00 - h00, v01 - h01);
            *(uint32_t*)(g_hid_hi + base1) = bfpair(v10, v11);
            *(uint32_t*)(g_hid_lo + base1) = bfpair(v10 - h10, v11 - h11);
        }
    }
}

// ---------------------------------------------------------------------------
// GEMM2 (HMMA): out[b,e,s] = hidden @ w2^T + b2  (smem-transpose epilogue)
// ---------------------------------------------------------------------------
__global__ __launch_bounds__(256, 2) void gemm2_tc(const float* __restrict__ b2,
                                                   float* __restrict__ out) {
    extern __shared__ char smem[];
    const uint32_t sbase = smem_u32(smem);
    const int tid = threadIdx.x;
    const int wid = tid >> 5, lane = tid & 31;
    const int n0 = blockIdx.x * 128;
    const int m0 = blockIdx.y * 128;
    const int warp_m = (wid & 1) * 64;
    const int warp_n = (wid >> 1) * 32;

    float acc[4][4][4];
    #pragma unroll
    for (int i = 0; i < 4; i++)
        #pragma unroll
        for (int j = 0; j < 4; j++)
            #pragma unroll
            for (int k = 0; k < 4; k++) acc[i][j][k] = 0.f;

    gemm_mainloop(smem, sbase, tid, lane, warp_m, warp_n, m0, n0,
                  g_hid_hi, g_hid_lo, g_w2_hi, g_w2_lo, acc);

    // ---- epilogue: acc -> smem T[m][e] -> transposed coalesced out stores ----
    float* T = (float*)smem;
    #pragma unroll
    for (int mf = 0; mf < 4; mf++) {
        #pragma unroll
        for (int nf = 0; nf < 4; nf++) {
            const int rm = warp_m + mf * 16 + (lane >> 2);
            const int cn = warp_n + nf * 8 + (lane & 3) * 2;
            T[rm * T_STRIDE + cn]           = acc[mf][nf][0];
            T[rm * T_STRIDE + cn + 1]       = acc[mf][nf][1];
            T[(rm + 8) * T_STRIDE + cn]     = acc[mf][nf][2];
            T[(rm + 8) * T_STRIDE + cn + 1] = acc[mf][nf][3];
        }
    }
    __syncthreads();
    {
        const int e    = tid & 127;
        const int half = tid >> 7;
        const int bidx = m0 >> 10;
        const int sb   = m0 & (HW - 1);
        const float bv = b2[n0 + e];
        float* orow = out + ((size_t)bidx * CCH + n0 + e) * HW + sb + half * 64;
        #pragma unroll
        for (int grp = 0; grp < 16; grp++) {
            const int mb = half * 64 + grp * 4;
            float4 o;
            o.x = T[(mb + 0) * T_STRIDE + e] + bv;
            o.y = T[(mb + 1) * T_STRIDE + e] + bv;
            o.z = T[(mb + 2) * T_STRIDE + e] + bv;
            o.w = T[(mb + 3) * T_STRIDE + e] + bv;
            *(float4*)(orow + grp * 4) = o;
        }
    }
}

// ---------------------------------------------------------------------------
extern "C" void kernel_launch(void* const* d_in, const int* in_sizes, int n_in,
                              void* d_out, int out_size) {
    const float* x = 0; const float* lnw = 0; const float* lnb = 0;
    const float* w1 = 0; const float* b1 = 0; const float* w2 = 0;
    const float* b2 = 0;
    for (int i = 0; i < n_in; i++) {
        const float* p = (const float*)d_in[i];
        switch (in_sizes[i]) {
            case 67108864: x = p; break;
            case 524288:   if (!lnw) lnw = p; else lnb = p; break;
            case 262144:   if (!w1)  w1  = p; else w2  = p; break;
            case 512:      if (!b1)  b1  = p; else b2  = p; break;
            default: break;
        }
    }
    float* out = (float*)d_out;

    cudaFuncSetAttribute(gemm1_tc, cudaFuncAttributeMaxDynamicSharedMemorySize, SMEM_TOTAL);
    cudaFuncSetAttribute(gemm2_tc, cudaFuncAttributeMaxDynamicSharedMemorySize, SMEM_TOTAL);

    ln_stats_kernel<<<BATCH, 1024>>>(x);
    prep_w_kernel<<<256, 256>>>(w1, w2);
    prep_a_kernel<<<(BATCH * HW) / 128, 256>>>(x, lnw, lnb);
    dim3 grid(CCH / 128, (BATCH * HW) / 128);  // (4, 1024)
    gemm1_tc<<<grid, 256, SMEM_TOTAL>>>(b1);
    gemm2_tc<<<grid, 256, SMEM_TOTAL>>>(b2, out);
}

// round 15
// speedup vs baseline: 1.8724x; 1.0338x over previous
#include <cuda_runtime.h>
#include <cuda_bf16.h>
#include <stdint.h>
#include <math.h>

// Problem constants
#define BATCH 128
#define CCH   512
#define HW    1024
#define EPSV  1e-5f

// GEMM tiling: CTA 128x128, K-chunk 32, 2-stage pipeline packed in 128B rows
#define BK      32
#define NCHUNK  (CCH / BK)    // 16

#define OFF_AH  0
#define OFF_AL  16384
#define OFF_BH  32768
#define OFF_BL  49152
#define T_STRIDE 129
#define SMEM_TOTAL (128 * T_STRIDE * 4)   // 66048 >= 65536 mainloop need

// scratch (no allocs allowed)
__device__ float g_mu[BATCH];
__device__ float g_rstd[BATCH];
__device__ __nv_bfloat16 g_a_hi[(size_t)BATCH * HW * CCH];    // 128 MiB  LN(x) hi
__device__ __nv_bfloat16 g_a_lo[(size_t)BATCH * HW * CCH];    // 128 MiB  LN(x) lo
__device__ __nv_bfloat16 g_hid_hi[(size_t)BATCH * HW * CCH];  // 128 MiB
__device__ __nv_bfloat16 g_hid_lo[(size_t)BATCH * HW * CCH];  // 128 MiB
__device__ __nv_bfloat16 g_w1_hi[CCH * CCH];
__device__ __nv_bfloat16 g_w1_lo[CCH * CCH];
__device__ __nv_bfloat16 g_w2_hi[CCH * CCH];
__device__ __nv_bfloat16 g_w2_lo[CCH * CCH];

// ---------------------------------------------------------------------------
// helpers
// ---------------------------------------------------------------------------
__device__ __forceinline__ uint32_t smem_u32(const void* p) {
    uint32_t a;
    asm("{ .reg .u64 t; cvta.to.shared.u64 t, %1; cvt.u32.u64 %0, t; }" : "=r"(a) : "l"(p));
    return a;
}
__device__ __forceinline__ uint32_t swz(uint32_t off) { return off ^ ((off >> 3) & 0x70); }

__device__ __forceinline__ uint32_t bfpair(float a, float b) {
    __nv_bfloat162 t = __floats2bfloat162_rn(a, b);
    return *reinterpret_cast<uint32_t*>(&t);
}

__device__ __forceinline__ void cpasync16(uint32_t saddr, const void* gptr) {
    asm volatile("cp.async.cg.shared.global [%0], [%1], 16;" :: "r"(saddr), "l"(gptr));
}
#define CP_COMMIT() asm volatile("cp.async.commit_group;" ::: "memory")
#define CP_WAIT0()  asm volatile("cp.async.wait_group 0;" ::: "memory")
#define CP_WAIT1()  asm volatile("cp.async.wait_group 1;" ::: "memory")

__device__ __forceinline__ void ldsm4(uint32_t& r0, uint32_t& r1, uint32_t& r2,
                                      uint32_t& r3, uint32_t addr) {
    asm volatile("ldmatrix.sync.aligned.m8n8.x4.shared.b16 {%0,%1,%2,%3}, [%4];"
                 : "=r"(r0), "=r"(r1), "=r"(r2), "=r"(r3) : "r"(addr));
}

__device__ __forceinline__ void mma16816(float* c, const uint32_t* a,
                                         uint32_t b0, uint32_t b1) {
    asm volatile(
        "mma.sync.aligned.m16n8k16.row.col.f32.bf16.bf16.f32 "
        "{%0,%1,%2,%3}, {%4,%5,%6,%7}, {%8,%9}, {%0,%1,%2,%3};"
        : "+f"(c[0]), "+f"(c[1]), "+f"(c[2]), "+f"(c[3])
        : "r"(a[0]), "r"(a[1]), "r"(a[2]), "r"(a[3]), "r"(b0), "r"(b1));
}

// ---------------------------------------------------------------------------
// Kernel 1: per-sample mean / rstd
// ---------------------------------------------------------------------------
__global__ __launch_bounds__(1024) void ln_stats_kernel(const float* __restrict__ x) {
    const int b = blockIdx.x;
    const float4* xb = reinterpret_cast<const float4*>(x) + (size_t)b * (CCH * HW / 4);
    float s = 0.f, ss = 0.f;
    for (int i = threadIdx.x; i < CCH * HW / 4; i += blockDim.x) {
        float4 v = xb[i];
        s  += (v.x + v.y) + (v.z + v.w);
        ss += (v.x * v.x + v.y * v.y) + (v.z * v.z + v.w * v.w);
    }
    #pragma unroll
    for (int o = 16; o; o >>= 1) {
        s  += __shfl_xor_sync(0xFFFFFFFFu, s, o);
        ss += __shfl_xor_sync(0xFFFFFFFFu, ss, o);
    }
    __shared__ float sh[2][32];
    const int w = threadIdx.x >> 5, l = threadIdx.x & 31;
    if (l == 0) { sh[0][w] = s; sh[1][w] = ss; }
    __syncthreads();
    if (w == 0) {
        s = sh[0][l]; ss = sh[1][l];
        #pragma unroll
        for (int o = 16; o; o >>= 1) {
            s  += __shfl_xor_sync(0xFFFFFFFFu, s, o);
            ss += __shfl_xor_sync(0xFFFFFFFFu, ss, o);
        }
        if (l == 0) {
            const float inv = 1.f / (float)(CCH * HW);
            const float mu = s * inv;
            const float var = ss * inv - mu * mu;
            g_mu[b] = mu;
            g_rstd[b] = rsqrtf(var + EPSV);
        }
    }
}

// ---------------------------------------------------------------------------
// prep_w: split w1/w2 to bf16 hi/lo planes (once)
// ---------------------------------------------------------------------------
__global__ __launch_bounds__(256) void prep_w_kernel(const float* __restrict__ w1,
                                                     const float* __restrict__ w2) {
    const int idx = (blockIdx.x * 256 + threadIdx.x) * 4;   // grid 256 -> covers 262144
    {
        float4 v = *(const float4*)(w1 + idx);
        float h0 = __bfloat162float(__float2bfloat16(v.x));
        float h1 = __bfloat162float(__float2bfloat16(v.y));
        float h2 = __bfloat162float(__float2bfloat16(v.z));
        float h3 = __bfloat162float(__float2bfloat16(v.w));
        *(uint2*)(g_w1_hi + idx) = make_uint2(bfpair(v.x, v.y), bfpair(v.z, v.w));
        *(uint2*)(g_w1_lo + idx) = make_uint2(bfpair(v.x - h0, v.y - h1), bfpair(v.z - h2, v.w - h3));
    }
    {
        float4 v = *(const float4*)(w2 + idx);
        float h0 = __bfloat162float(__float2bfloat16(v.x));
        float h1 = __bfloat162float(__float2bfloat16(v.y));
        float h2 = __bfloat162float(__float2bfloat16(v.z));
        float h3 = __bfloat162float(__float2bfloat16(v.w));
        *(uint2*)(g_w2_hi + idx) = make_uint2(bfpair(v.x, v.y), bfpair(v.z, v.w));
        *(uint2*)(g_w2_lo + idx) = make_uint2(bfpair(v.x - h0, v.y - h1), bfpair(v.z - h2, v.w - h3));
    }
}

// ---------------------------------------------------------------------------
// prep_a: LN(x) -> bf16 hi/lo planes in [m][c] (k-contiguous) layout (once)
// ---------------------------------------------------------------------------
__global__ __launch_bounds__(256) void prep_a_kernel(
    const float* __restrict__ x, const float* __restrict__ lnw,
    const float* __restrict__ lnb)
{
    const int m0 = blockIdx.x * 128;
    const int b  = m0 >> 10;
    const int s0 = m0 & (HW - 1);
    const float mu = g_mu[b], rstd = g_rstd[b];
    const float* xb = x + (size_t)b * CCH * HW;

    const int lc4 = (threadIdx.x & 15) * 4;
    const int lmr = (threadIdx.x >> 4) * 8;

    #pragma unroll 1
    for (int p = 0; p < 8; p++) {
        const int cbase = p * 64 + lc4;
        float vals[4][8];
        #pragma unroll
        for (int cc = 0; cc < 4; cc++) {
            const size_t rb = (size_t)(cbase + cc) * HW + s0 + lmr;
            float4 x0 = *(const float4*)(xb + rb);
            float4 x1 = *(const float4*)(xb + rb + 4);
            float4 w0 = *(const float4*)(lnw + rb);
            float4 w1v = *(const float4*)(lnw + rb + 4);
            float4 e0 = *(const float4*)(lnb + rb);
            float4 e1 = *(const float4*)(lnb + rb + 4);
            vals[cc][0] = fmaf((x0.x - mu) * rstd, w0.x, e0.x);
            vals[cc][1] = fmaf((x0.y - mu) * rstd, w0.y, e0.y);
            vals[cc][2] = fmaf((x0.z - mu) * rstd, w0.z, e0.z);
            vals[cc][3] = fmaf((x0.w - mu) * rstd, w0.w, e0.w);
            vals[cc][4] = fmaf((x1.x - mu) * rstd, w1v.x, e1.x);
            vals[cc][5] = fmaf((x1.y - mu) * rstd, w1v.y, e1.y);
            vals[cc][6] = fmaf((x1.z - mu) * rstd, w1v.z, e1.z);
            vals[cc][7] = fmaf((x1.w - mu) * rstd, w1v.w, e1.w);
        }
        #pragma unroll
        for (int j = 0; j < 8; j++) {
            const size_t base = (size_t)(m0 + lmr + j) * CCH + cbase;
            float v0 = vals[0][j], v1 = vals[1][j], v2 = vals[2][j], v3 = vals[3][j];
            float h0 = __bfloat162float(__float2bfloat16(v0));
            float h1 = __bfloat162float(__float2bfloat16(v1));
            float h2 = __bfloat162float(__float2bfloat16(v2));
            float h3 = __bfloat162float(__float2bfloat16(v3));
            *(uint2*)(g_a_hi + base) = make_uint2(bfpair(v0, v1), bfpair(v2, v3));
            *(uint2*)(g_a_lo + base) = make_uint2(bfpair(v0 - h0, v1 - h1), bfpair(v2 - h2, v3 - h3));
        }
    }
}

// ---------------------------------------------------------------------------
// Pipelined mainloop: 2-stage cp.async, both stages packed in each 128B row
//   stage s occupies 16B-units [s*4, s*4+4) of every row; BK=32 per stage.
// ---------------------------------------------------------------------------
__device__ __forceinline__ void pipe_issue(
    uint32_t sbase, int row_, int ch0, int stage, int c0, int m0, int n0,
    const __nv_bfloat16* __restrict__ a_hi, const __nv_bfloat16* __restrict__ a_lo,
    const __nv_bfloat16* __restrict__ w_hi, const __nv_bfloat16* __restrict__ w_lo)
{
    const size_t ab = (size_t)(m0 + row_) * CCH + c0;
    const size_t bb = (size_t)(n0 + row_) * CCH + c0;
    #pragma unroll
    for (int ch = 0; ch < 2; ch++) {
        const uint32_t off = swz((uint32_t)(row_ * 128 + (stage * 4 + ch0 + ch) * 16));
        const int eo = (ch0 + ch) * 8;
        cpasync16(sbase + OFF_AH + off, a_hi + ab + eo);
        cpasync16(sbase + OFF_AL + off, a_lo + ab + eo);
        cpasync16(sbase + OFF_BH + off, w_hi + bb + eo);
        cpasync16(sbase + OFF_BL + off, w_lo + bb + eo);
    }
    CP_COMMIT();
}

__device__ __forceinline__ void gemm_mainloop(
    uint32_t sbase, int tid, int lane,
    int warp_m, int warp_n, int m0, int n0,
    const __nv_bfloat16* __restrict__ a_hi, const __nv_bfloat16* __restrict__ a_lo,
    const __nv_bfloat16* __restrict__ w_hi, const __nv_bfloat16* __restrict__ w_lo,
    float acc[4][4][4])
{
    const int row_ = tid >> 1;          // loader row (m for A, n for B)
    const int ch0  = (tid & 1) * 2;     // 2 of the 4 16B units per stage-half

    // prologue: chunk 0 -> stage 0
    pipe_issue(sbase, row_, ch0, 0, 0, m0, n0, a_hi, a_lo, w_hi, w_lo);

    #pragma unroll 1
    for (int kt = 0; kt < NCHUNK; kt++) {
        const int stage = kt & 1;
        if (kt + 1 < NCHUNK) {
            pipe_issue(sbase, row_, ch0, (kt + 1) & 1, (kt + 1) * BK, m0, n0,
                       a_hi, a_lo, w_hi, w_lo);
            CP_WAIT1();     // chunk kt landed; kt+1 still in flight
        } else {
            CP_WAIT0();
        }
        __syncthreads();
        // ---- compute on stage: 2 k-steps of 16, 3-term split ----
        #pragma unroll
        for (int ks = 0; ks < 2; ks++) {
            uint32_t bhf[8], blf[8];
            #pragma unroll
            for (int g = 0; g < 2; g++) {
                const int nrow = warp_n + g * 16 + (lane & 7) + ((lane >> 4) & 1) * 8;
                const int chunk = stage * 4 + ks * 2 + ((lane >> 3) & 1);
                const uint32_t off = swz((uint32_t)(nrow * 128 + chunk * 16));
                ldsm4(bhf[g*4+0], bhf[g*4+1], bhf[g*4+2], bhf[g*4+3], sbase + OFF_BH + off);
                ldsm4(blf[g*4+0], blf[g*4+1], blf[g*4+2], blf[g*4+3], sbase + OFF_BL + off);
            }
            #pragma unroll
            for (int mf = 0; mf < 4; mf++) {
                const int mrow = warp_m + mf * 16 + (lane & 15);
                const int chunk = stage * 4 + ks * 2 + (lane >> 4);
                const uint32_t off = swz((uint32_t)(mrow * 128 + chunk * 16));
                uint32_t ah[4], al[4];
                ldsm4(ah[0], ah[1], ah[2], ah[3], sbase + OFF_AH + off);
                ldsm4(al[0], al[1], al[2], al[3], sbase + OFF_AL + off);
                #pragma unroll
                for (int nf = 0; nf < 4; nf++) {
                    mma16816(acc[mf][nf], ah, bhf[nf*2], bhf[nf*2+1]);
                    mma16816(acc[mf][nf], ah, blf[nf*2], blf[nf*2+1]);
                    mma16816(acc[mf][nf], al, bhf[nf*2], bhf[nf*2+1]);
                }
            }
        }
        __syncthreads();   // compute done before next iter overwrites this stage
    }
}

// ---------------------------------------------------------------------------
// GEMM1 (HMMA): hidden = relu(a @ w1^T + b1) -> bf16 hi/lo planes
// ---------------------------------------------------------------------------
__global__ __launch_bounds__(256, 2) void gemm1_tc(const float* __restrict__ b1) {
    extern __shared__ char smem[];
    const uint32_t sbase = smem_u32(smem);
    const int tid = threadIdx.x;
    const int wid = tid >> 5, lane = tid & 31;
    const int n0 = blockIdx.x * 128;
    const int m0 = blockIdx.y * 128;
    const int warp_m = (wid & 1) * 64;
    const int warp_n = (wid >> 1) * 32;

    float acc[4][4][4];
    #pragma unroll
    for (int i = 0; i < 4; i++)
        #pragma unroll
        for (int j = 0; j < 4; j++)
            #pragma unroll
            for (int k = 0; k < 4; k++) acc[i][j][k] = 0.f;

    gemm_mainloop(sbase, tid, lane, warp_m, warp_n, m0, n0,
                  g_a_hi, g_a_lo, g_w1_hi, g_w1_lo, acc);

    // ---- epilogue: bias + relu + split -> hidden planes (register-direct) ----
    #pragma unroll
    for (int mf = 0; mf < 4; mf++) {
        #pragma unroll
        for (int nf = 0; nf < 4; nf++) {
            const int rm = warp_m + mf * 16 + (lane >> 2);
            const int cn = warp_n + nf * 8 + (lane & 3) * 2;
            const float bv0 = b1[n0 + cn], bv1 = b1[n0 + cn + 1];
            float v00 = fmaxf(acc[mf][nf][0] + bv0, 0.f);
            float v01 = fmaxf(acc[mf][nf][1] + bv1, 0.f);
            float v10 = fmaxf(acc[mf][nf][2] + bv0, 0.f);
            float v11 = fmaxf(acc[mf][nf][3] + bv1, 0.f);
            const size_t base0 = (size_t)(m0 + rm) * CCH + n0 + cn;
            const size_t base1 = base0 + 8 * CCH;
            float h00 = __bfloat162float(__float2bfloat16(v00));
            float h01 = __bfloat162float(__float2bfloat16(v01));
            float h10 = __bfloat162float(__float2bfloat16(v10));
            float h11 = __bfloat162float(__float2bfloat16(v11));
            *(uint32_t*)(g_hid_hi + base0) = bfpair(v00, v01);
            *(uint32_t*)(g_hid_lo + base0) = bfpair(v00 - h00, v01 - h01);
            *(uint32_t*)(g_hid_hi + base1) = bfpair(v10, v11);
            *(uint32_t*)(g_hid_lo + base1) = bfpair(v10 - h10, v11 - h11);
        }
    }
}

// ---------------------------------------------------------------------------
// GEMM2 (HMMA): out[b,e,s] = hidden @ w2^T + b2  (smem-transpose epilogue)
// ---------------------------------------------------------------------------
__global__ __launch_bounds__(256, 2) void gemm2_tc(const float* __restrict__ b2,
                                                   float* __restrict__ out) {
    extern __shared__ char smem[];
    const uint32_t sbase = smem_u32(smem);
    const int tid = threadIdx.x;
    const int wid = tid >> 5, lane = tid & 31;
    const int n0 = blockIdx.x * 128;
    const int m0 = blockIdx.y * 128;
    const int warp_m = (wid & 1) * 64;
    const int warp_n = (wid >> 1) * 32;

    float acc[4][4][4];
    #pragma unroll
    for (int i = 0; i < 4; i++)
        #pragma unroll
        for (int j = 0; j < 4; j++)
            #pragma unroll
            for (int k = 0; k < 4; k++) acc[i][j][k] = 0.f;

    gemm_mainloop(sbase, tid, lane, warp_m, warp_n, m0, n0,
                  g_hid_hi, g_hid_lo, g_w2_hi, g_w2_lo, acc);

    // ---- epilogue: acc -> smem T[m][e] -> transposed coalesced out stores ----
    float* T = (float*)smem;
    #pragma unroll
    for (int mf = 0; mf < 4; mf++) {
        #pragma unroll
        for (int nf = 0; nf < 4; nf++) {
            const int rm = warp_m + mf * 16 + (lane >> 2);
            const int cn = warp_n + nf * 8 + (lane & 3) * 2;
            T[rm * T_STRIDE + cn]           = acc[mf][nf][0];
            T[rm * T_STRIDE + cn + 1]       = acc[mf][nf][1];
            T[(rm + 8) * T_STRIDE + cn]     = acc[mf][nf][2];
            T[(rm + 8) * T_STRIDE + cn + 1] = acc[mf][nf][3];
        }
    }
    __syncthreads();
    {
        const int e    = tid & 127;
        const int half = tid >> 7;
        const int bidx = m0 >> 10;
        const int sb   = m0 & (HW - 1);
        const float bv = b2[n0 + e];
        float* orow = out + ((size_t)bidx * CCH + n0 + e) * HW + sb + half * 64;
        #pragma unroll
        for (int grp = 0; grp < 16; grp++) {
            const int mb = half * 64 + grp * 4;
            float4 o;
            o.x = T[(mb + 0) * T_STRIDE + e] + bv;
            o.y = T[(mb + 1) * T_STRIDE + e] + bv;
            o.z = T[(mb + 2) * T_STRIDE + e] + bv;
            o.w = T[(mb + 3) * T_STRIDE + e] + bv;
            *(float4*)(orow + grp * 4) = o;
        }
    }
}

// ---------------------------------------------------------------------------
extern "C" void kernel_launch(void* const* d_in, const int* in_sizes, int n_in,
                              void* d_out, int out_size) {
    const float* x = 0; const float* lnw = 0; const float* lnb = 0;
    const float* w1 = 0; const float* b1 = 0; const float* w2 = 0;
    const float* b2 = 0;
    for (int i = 0; i < n_in; i++) {
        const float* p = (const float*)d_in[i];
        switch (in_sizes[i]) {
            case 67108864: x = p; break;
            case 524288:   if (!lnw) lnw = p; else lnb = p; break;
            case 262144:   if (!w1)  w1  = p; else w2  = p; break;
            case 512:      if (!b1)  b1  = p; else b2  = p; break;
            default: break;
        }
    }
    float* out = (float*)d_out;

    cudaFuncSetAttribute(gemm1_tc, cudaFuncAttributeMaxDynamicSharedMemorySize, SMEM_TOTAL);
    cudaFuncSetAttribute(gemm2_tc, cudaFuncAttributeMaxDynamicSharedMemorySize, SMEM_TOTAL);

    ln_stats_kernel<<<BATCH, 1024>>>(x);
    prep_w_kernel<<<256, 256>>>(w1, w2);
    prep_a_kernel<<<(BATCH * HW) / 128, 256>>>(x, lnw, lnb);
    dim3 grid(CCH / 128, (BATCH * HW) / 128);  // (4, 1024)
    gemm1_tc<<<grid, 256, SMEM_TOTAL>>>(b1);
    gemm2_tc<<<grid, 256, SMEM_TOTAL>>>(b2, out);
}

// round 17
// speedup vs baseline: 2.3839x; 1.2732x over previous
#include <cuda_runtime.h>
#include <cuda_fp16.h>
#include <stdint.h>
#include <math.h>

// Problem constants
#define BATCH 128
#define CCH   512
#define HW    1024
#define EPSV  1e-5f

// GEMM tiling: CTA 128x128, K-chunk 32, 2-stage pipeline packed in 128B rows
#define BK      32
#define NCHUNK  (CCH / BK)    // 16

#define OFF_AH  0
#define OFF_AL  16384
#define OFF_BH  32768
#define T_STRIDE 129
#define SMEM_TOTAL (128 * T_STRIDE * 4)   // 66048 (epilogue T dominates; mainloop 48KB)

// scratch (no allocs allowed)
__device__ float g_mu[BATCH];
__device__ float g_rstd[BATCH];
__device__ __half g_a_hi[(size_t)BATCH * HW * CCH];    // 128 MiB  LN(x) hi
__device__ __half g_a_lo[(size_t)BATCH * HW * CCH];    // 128 MiB  LN(x) lo
__device__ __half g_hid_hi[(size_t)BATCH * HW * CCH];  // 128 MiB
__device__ __half g_hid_lo[(size_t)BATCH * HW * CCH];  // 128 MiB
__device__ __half g_w1_hi[CCH * CCH];
__device__ __half g_w2_hi[CCH * CCH];

// ---------------------------------------------------------------------------
// helpers
// ---------------------------------------------------------------------------
__device__ __forceinline__ uint32_t smem_u32(const void* p) {
    uint32_t a;
    asm("{ .reg .u64 t; cvta.to.shared.u64 t, %1; cvt.u32.u64 %0, t; }" : "=r"(a) : "l"(p));
    return a;
}
__device__ __forceinline__ uint32_t swz(uint32_t off) { return off ^ ((off >> 3) & 0x70); }

__device__ __forceinline__ uint32_t hfpair(float a, float b) {
    __half2 t = __floats2half2_rn(a, b);
    return *reinterpret_cast<uint32_t*>(&t);
}

__device__ __forceinline__ void cpasync16(uint32_t saddr, const void* gptr) {
    asm volatile("cp.async.cg.shared.global [%0], [%1], 16;" :: "r"(saddr), "l"(gptr));
}
#define CP_COMMIT() asm volatile("cp.async.commit_group;" ::: "memory")
#define CP_WAIT0()  asm volatile("cp.async.wait_group 0;" ::: "memory")
#define CP_WAIT1()  asm volatile("cp.async.wait_group 1;" ::: "memory")

__device__ __forceinline__ void ldsm4(uint32_t& r0, uint32_t& r1, uint32_t& r2,
                                      uint32_t& r3, uint32_t addr) {
    asm volatile("ldmatrix.sync.aligned.m8n8.x4.shared.b16 {%0,%1,%2,%3}, [%4];"
                 : "=r"(r0), "=r"(r1), "=r"(r2), "=r"(r3) : "r"(addr));
}

__device__ __forceinline__ void mma16816(float* c, const uint32_t* a,
                                         uint32_t b0, uint32_t b1) {
    asm volatile(
        "mma.sync.aligned.m16n8k16.row.col.f32.f16.f16.f32 "
        "{%0,%1,%2,%3}, {%4,%5,%6,%7}, {%8,%9}, {%0,%1,%2,%3};"
        : "+f"(c[0]), "+f"(c[1]), "+f"(c[2]), "+f"(c[3])
        : "r"(a[0]), "r"(a[1]), "r"(a[2]), "r"(a[3]), "r"(b0), "r"(b1));
}

// ---------------------------------------------------------------------------
// Kernel 1: per-sample mean / rstd
// ---------------------------------------------------------------------------
__global__ __launch_bounds__(1024) void ln_stats_kernel(const float* __restrict__ x) {
    const int b = blockIdx.x;
    const float4* xb = reinterpret_cast<const float4*>(x) + (size_t)b * (CCH * HW / 4);
    float s = 0.f, ss = 0.f;
    for (int i = threadIdx.x; i < CCH * HW / 4; i += blockDim.x) {
        float4 v = xb[i];
        s  += (v.x + v.y) + (v.z + v.w);
        ss += (v.x * v.x + v.y * v.y) + (v.z * v.z + v.w * v.w);
    }
    #pragma unroll
    for (int o = 16; o; o >>= 1) {
        s  += __shfl_xor_sync(0xFFFFFFFFu, s, o);
        ss += __shfl_xor_sync(0xFFFFFFFFu, ss, o);
    }
    __shared__ float sh[2][32];
    const int w = threadIdx.x >> 5, l = threadIdx.x & 31;
    if (l == 0) { sh[0][w] = s; sh[1][w] = ss; }
    __syncthreads();
    if (w == 0) {
        s = sh[0][l]; ss = sh[1][l];
        #pragma unroll
        for (int o = 16; o; o >>= 1) {
            s  += __shfl_xor_sync(0xFFFFFFFFu, s, o);
            ss += __shfl_xor_sync(0xFFFFFFFFu, ss, o);
        }
        if (l == 0) {
            const float inv = 1.f / (float)(CCH * HW);
            const float mu = s * inv;
            const float var = ss * inv - mu * mu;
            g_mu[b] = mu;
            g_rstd[b] = rsqrtf(var + EPSV);
        }
    }
}

// ---------------------------------------------------------------------------
// prep_w: round w1/w2 to fp16 (once)
// ---------------------------------------------------------------------------
__global__ __launch_bounds__(256) void prep_w_kernel(const float* __restrict__ w1,
                                                     const float* __restrict__ w2) {
    const int idx = (blockIdx.x * 256 + threadIdx.x) * 4;   // grid 256 -> 262144
    {
        float4 v = *(const float4*)(w1 + idx);
        *(uint2*)(g_w1_hi + idx) = make_uint2(hfpair(v.x, v.y), hfpair(v.z, v.w));
    }
    {
        float4 v = *(const float4*)(w2 + idx);
        *(uint2*)(g_w2_hi + idx) = make_uint2(hfpair(v.x, v.y), hfpair(v.z, v.w));
    }
}

// ---------------------------------------------------------------------------
// prep_a: LN(x) -> fp16 hi/lo planes in [m][c] (k-contiguous) layout (once)
// ---------------------------------------------------------------------------
__global__ __launch_bounds__(256) void prep_a_kernel(
    const float* __restrict__ x, const float* __restrict__ lnw,
    const float* __restrict__ lnb)
{
    const int m0 = blockIdx.x * 128;
    const int b  = m0 >> 10;
    const int s0 = m0 & (HW - 1);
    const float mu = g_mu[b], rstd = g_rstd[b];
    const float* xb = x + (size_t)b * CCH * HW;

    const int lc4 = (threadIdx.x & 15) * 4;
    const int lmr = (threadIdx.x >> 4) * 8;

    #pragma unroll 1
    for (int p = 0; p < 8; p++) {
        const int cbase = p * 64 + lc4;
        float vals[4][8];
        #pragma unroll
        for (int cc = 0; cc < 4; cc++) {
            const size_t rb = (size_t)(cbase + cc) * HW + s0 + lmr;
            float4 x0 = *(const float4*)(xb + rb);
            float4 x1 = *(const float4*)(xb + rb + 4);
            float4 w0 = *(const float4*)(lnw + rb);
            float4 w1v = *(const float4*)(lnw + rb + 4);
            float4 e0 = *(const float4*)(lnb + rb);
            float4 e1 = *(const float4*)(lnb + rb + 4);
            vals[cc][0] = fmaf((x0.x - mu) * rstd, w0.x, e0.x);
            vals[cc][1] = fmaf((x0.y - mu) * rstd, w0.y, e0.y);
            vals[cc][2] = fmaf((x0.z - mu) * rstd, w0.z, e0.z);
            vals[cc][3] = fmaf((x0.w - mu) * rstd, w0.w, e0.w);
            vals[cc][4] = fmaf((x1.x - mu) * rstd, w1v.x, e1.x);
            vals[cc][5] = fmaf((x1.y - mu) * rstd, w1v.y, e1.y);
            vals[cc][6] = fmaf((x1.z - mu) * rstd, w1v.z, e1.z);
            vals[cc][7] = fmaf((x1.w - mu) * rstd, w1v.w, e1.w);
        }
        #pragma unroll
        for (int j = 0; j < 8; j++) {
            const size_t base = (size_t)(m0 + lmr + j) * CCH + cbase;
            float v0 = vals[0][j], v1 = vals[1][j], v2 = vals[2][j], v3 = vals[3][j];
            float h0 = __half2float(__float2half(v0));
            float h1 = __half2float(__float2half(v1));
            float h2 = __half2float(__float2half(v2));
            float h3 = __half2float(__float2half(v3));
            *(uint2*)(g_a_hi + base) = make_uint2(hfpair(v0, v1), hfpair(v2, v3));
            *(uint2*)(g_a_lo + base) = make_uint2(hfpair(v0 - h0, v1 - h1), hfpair(v2 - h2, v3 - h3));
        }
    }
}

// ---------------------------------------------------------------------------
// Pipelined mainloop: 2-stage cp.async, stages packed in each 128B row
//   stage s owns 16B-units [s*4, s*4+4); planes: A hi, A lo, B hi.
// ---------------------------------------------------------------------------
__device__ __forceinline__ void pipe_issue(
    uint32_t sbase, int row_, int ch0, int stage, int c0, int m0, int n0,
    const __half* __restrict__ a_hi, const __half* __restrict__ a_lo,
    const __half* __restrict__ w_hi)
{
    const size_t ab = (size_t)(m0 + row_) * CCH + c0;
    const size_t bb = (size_t)(n0 + row_) * CCH + c0;
    #pragma unroll
    for (int ch = 0; ch < 2; ch++) {
        const uint32_t off = swz((uint32_t)(row_ * 128 + (stage * 4 + ch0 + ch) * 16));
        const int eo = (ch0 + ch) * 8;
        cpasync16(sbase + OFF_AH + off, a_hi + ab + eo);
        cpasync16(sbase + OFF_AL + off, a_lo + ab + eo);
        cpasync16(sbase + OFF_BH + off, w_hi + bb + eo);
    }
    CP_COMMIT();
}

__device__ __forceinline__ void gemm_mainloop(
    uint32_t sbase, int tid, int lane,
    int warp_m, int warp_n, int m0, int n0,
    const __half* __restrict__ a_hi, const __half* __restrict__ a_lo,
    const __half* __restrict__ w_hi,
    float acc[4][4][4])
{
    const int row_ = tid >> 1;          // loader row (m for A, n for B)
    const int ch0  = (tid & 1) * 2;     // 2 of the 4 16B units per stage-half

    // prologue: chunk 0 -> stage 0
    pipe_issue(sbase, row_, ch0, 0, 0, m0, n0, a_hi, a_lo, w_hi);

    #pragma unroll 1
    for (int kt = 0; kt < NCHUNK; kt++) {
        const int stage = kt & 1;
        if (kt + 1 < NCHUNK) {
            pipe_issue(sbase, row_, ch0, (kt + 1) & 1, (kt + 1) * BK, m0, n0,
                       a_hi, a_lo, w_hi);
            CP_WAIT1();     // chunk kt landed; kt+1 still in flight
        } else {
            CP_WAIT0();
        }
        __syncthreads();
        // ---- compute on stage: 2 k-steps of 16, 2-term split ----
        #pragma unroll
        for (int ks = 0; ks < 2; ks++) {
            uint32_t bhf[8];
            #pragma unroll
            for (int g = 0; g < 2; g++) {
                const int nrow = warp_n + g * 16 + (lane & 7) + ((lane >> 4) & 1) * 8;
                const int chunk = stage * 4 + ks * 2 + ((lane >> 3) & 1);
                const uint32_t off = swz((uint32_t)(nrow * 128 + chunk * 16));
                ldsm4(bhf[g*4+0], bhf[g*4+1], bhf[g*4+2], bhf[g*4+3], sbase + OFF_BH + off);
            }
            #pragma unroll
            for (int mf = 0; mf < 4; mf++) {
                const int mrow = warp_m + mf * 16 + (lane & 15);
                const int chunk = stage * 4 + ks * 2 + (lane >> 4);
                const uint32_t off = swz((uint32_t)(mrow * 128 + chunk * 16));
                uint32_t ah[4], al[4];
                ldsm4(ah[0], ah[1], ah[2], ah[3], sbase + OFF_AH + off);
                ldsm4(al[0], al[1], al[2], al[3], sbase + OFF_AL + off);
                #pragma unroll
                for (int nf = 0; nf < 4; nf++) {
                    mma16816(acc[mf][nf], ah, bhf[nf*2], bhf[nf*2+1]);
                    mma16816(acc[mf][nf], al, bhf[nf*2], bhf[nf*2+1]);
                }
            }
        }
        __syncthreads();   // compute done before next iter overwrites this stage
    }
}

// ---------------------------------------------------------------------------
// GEMM1 (HMMA): hidden = relu(a @ w1^T + b1) -> fp16 hi/lo planes
// ---------------------------------------------------------------------------
__global__ __launch_bounds__(256, 2) void gemm1_tc(const float* __restrict__ b1) {
    extern __shared__ char smem[];
    const uint32_t sbase = smem_u32(smem);
    const int tid = threadIdx.x;
    const int wid = tid >> 5, lane = tid & 31;
    const int n0 = blockIdx.x * 128;
    const int m0 = blockIdx.y * 128;
    const int warp_m = (wid & 1) * 64;
    const int warp_n = (wid >> 1) * 32;

    float acc[4][4][4];
    #pragma unroll
    for (int i = 0; i < 4; i++)
        #pragma unroll
        for (int j = 0; j < 4; j++)
            #pragma unroll
            for (int k = 0; k < 4; k++) acc[i][j][k] = 0.f;

    gemm_mainloop(sbase, tid, lane, warp_m, warp_n, m0, n0,
                  g_a_hi, g_a_lo, g_w1_hi, acc);

    // ---- epilogue: bias + relu + fp16 split -> hidden planes ----
    #pragma unroll
    for (int mf = 0; mf < 4; mf++) {
        #pragma unroll
        for (int nf = 0; nf < 4; nf++) {
            const int rm = warp_m + mf * 16 + (lane >> 2);
            const int cn = warp_n + nf * 8 + (lane & 3) * 2;
            const float bv0 = b1[n0 + cn], bv1 = b1[n0 + cn + 1];
            float v00 = fmaxf(acc[mf][nf][0] + bv0, 0.f);
            float v01 = fmaxf(acc[mf][nf][1] + bv1, 0.f);
            float v10 = fmaxf(acc[mf][nf][2] + bv0, 0.f);
            float v11 = fmaxf(acc[mf][nf][3] + bv1, 0.f);
            const size_t base0 = (size_t)(m0 + rm) * CCH + n0 + cn;
            const size_t base1 = base0 + 8 * CCH;
            float h00 = __half2float(__float2half(v00));
            float h01 = __half2float(__float2half(v01));
            float h10 = __half2float(__float2half(v10));
            float h11 = __half2float(__float2half(v11));
            *(uint32_t*)(g_hid_hi + base0) = hfpair(v00, v01);
            *(uint32_t*)(g_hid_lo + base0) = hfpair(v00 - h00, v01 - h01);
            *(uint32_t*)(g_hid_hi + base1) = hfpair(v10, v11);
            *(uint32_t*)(g_hid_lo + base1) = hfpair(v10 - h10, v11 - h11);
        }
    }
}

// ---------------------------------------------------------------------------
// GEMM2 (HMMA): out[b,e,s] = hidden @ w2^T + b2  (smem-transpose epilogue)
// ---------------------------------------------------------------------------
__global__ __launch_bounds__(256, 2) void gemm2_tc(const float* __restrict__ b2,
                                                   float* __restrict__ out) {
    extern __shared__ char smem[];
    const uint32_t sbase = smem_u32(smem);
    const int tid = threadIdx.x;
    const int wid = tid >> 5, lane = tid & 31;
    const int n0 = blockIdx.x * 128;
    const int m0 = blockIdx.y * 128;
    const int warp_m = (wid & 1) * 64;
    const int warp_n = (wid >> 1) * 32;

    float acc[4][4][4];
    #pragma unroll
    for (int i = 0; i < 4; i++)
        #pragma unroll
        for (int j = 0; j < 4; j++)
            #pragma unroll
            for (int k = 0; k < 4; k++) acc[i][j][k] = 0.f;

    gemm_mainloop(sbase, tid, lane, warp_m, warp_n, m0, n0,
                  g_hid_hi, g_hid_lo, g_w2_hi, acc);

    // ---- epilogue: acc -> smem T[m][e] -> transposed coalesced out stores ----
    float* T = (float*)smem;
    #pragma unroll
    for (int mf = 0; mf < 4; mf++) {
        #pragma unroll
        for (int nf = 0; nf < 4; nf++) {
            const int rm = warp_m + mf * 16 + (lane >> 2);
            const int cn = warp_n + nf * 8 + (lane & 3) * 2;
            T[rm * T_STRIDE + cn]           = acc[mf][nf][0];
            T[rm * T_STRIDE + cn + 1]       = acc[mf][nf][1];
            T[(rm + 8) * T_STRIDE + cn]     = acc[mf][nf][2];
            T[(rm + 8) * T_STRIDE + cn + 1] = acc[mf][nf][3];
        }
    }
    __syncthreads();
    {
        const int e    = tid & 127;
        const int half = tid >> 7;
        const int bidx = m0 >> 10;
        const int sb   = m0 & (HW - 1);
        const float bv = b2[n0 + e];
        float* orow = out + ((size_t)bidx * CCH + n0 + e) * HW + sb + half * 64;
        #pragma unroll
        for (int grp = 0; grp < 16; grp++) {
            const int mb = half * 64 + grp * 4;
            float4 o;
            o.x = T[(mb + 0) * T_STRIDE + e] + bv;
            o.y = T[(mb + 1) * T_STRIDE + e] + bv;
            o.z = T[(mb + 2) * T_STRIDE + e] + bv;
            o.w = T[(mb + 3) * T_STRIDE + e] + bv;
            *(float4*)(orow + grp * 4) = o;
        }
    }
}

// ---------------------------------------------------------------------------
extern "C" void kernel_launch(void* const* d_in, const int* in_sizes, int n_in,
                              void* d_out, int out_size) {
    const float* x = 0; const float* lnw = 0; const float* lnb = 0;
    const float* w1 = 0; const float* b1 = 0; const float* w2 = 0;
    const float* b2 = 0;
    for (int i = 0; i < n_in; i++) {
        const float* p = (const float*)d_in[i];
        switch (in_sizes[i]) {
            case 67108864: x = p; break;
            case 524288:   if (!lnw) lnw = p; else lnb = p; break;
            case 262144:   if (!w1)  w1  = p; else w2  = p; break;
            case 512:      if (!b1)  b1  = p; else b2  = p; break;
            default: break;
        }
    }
    float* out = (float*)d_out;

    cudaFuncSetAttribute(gemm1_tc, cudaFuncAttributeMaxDynamicSharedMemorySize, SMEM_TOTAL);
    cudaFuncSetAttribute(gemm2_tc, cudaFuncAttributeMaxDynamicSharedMemorySize, SMEM_TOTAL);

    ln_stats_kernel<<<BATCH, 1024>>>(x);
    prep_w_kernel<<<256, 256>>>(w1, w2);
    prep_a_kernel<<<(BATCH * HW) / 128, 256>>>(x, lnw, lnb);
    dim3 grid(CCH / 128, (BATCH * HW) / 128);  // (4, 1024)
    gemm1_tc<<<grid, 256, SMEM_TOTAL>>>(b1);
    gemm2_tc<<<grid, 256, SMEM_TOTAL>>>(b2, out);
}